// round 15
// baseline (speedup 1.0000x reference)
#include <cuda_runtime.h>
#include <cuda_bf16.h>
#include <math.h>
#include <stdint.h>

#define RB 4
#define CC 256
#define HWSZ 4096
#define OC2 18
#define PW 68
#define PHW 4624            // 68*68
#define PBASE 138           // 2*68 + 2

// ---------------- smem layout (bytes, dynamic) ------------------------------
// phase2 K-block 32: A buf = 256oc x 32ck bf16 hi(16K)+lo(16K); two bufs.
// B buf = 128px x 32ck bf16 hi(8K)+lo(8K); two bufs.
#define SM_A0   0
#define SM_A1   32768
#define SM_B0   65536
#define SM_B1   81920
#define SM_IDX  98304       // int[1152]
#define SM_WY   102912      // float[1152]
#define SM_WX   107520      // float[1152]
#define SM_TOTAL 112128
// phase1 reuse: A_off hi@0 lo@16384 (4K each); B 128x64 hi@32768 lo@49152;
// offs f32 [32][128] @32768.

// 128B-row swizzle (phase1)
#define SW(row, colb) (((uint32_t)(row) << 7) + \
    ((uint32_t)(colb) ^ (((uint32_t)(row) & 7) << 4)))
// 64B-row swizzle (phase2, K-block 32) — R8-proven
#define SW64(row, colb) (((uint32_t)(row) << 6) + \
    ((uint32_t)(colb) ^ (((uint32_t)(row) & 3) << 4) ^ (((uint32_t)(row) & 4) << 2)))

// ---------------- scratch ----------------------------------------------------
__device__ float g_padA[4734976];
__device__ float g_padB[4734976];
// phase2 weights: [r][kb72=kk*8+cb][oc256][j32], c = cb*32+j
__device__ __align__(16) __nv_bfloat16 g_whi[2359296];
__device__ __align__(16) __nv_bfloat16 g_wlo[2359296];
// offset weights: [r][kb36][ocp32][j64]
__device__ __align__(16) __nv_bfloat16 g_owhi[294912];
__device__ __align__(16) __nv_bfloat16 g_owlo[294912];

// ---------------- PTX helpers ----------------------------------------------
static __device__ __forceinline__ uint32_t smem_u32(const void* p) {
    uint32_t a;
    asm("{ .reg .u64 t; cvta.to.shared.u64 t, %1; cvt.u32.u64 %0, t; }" : "=r"(a) : "l"(p));
    return a;
}

#define LDSM4(r, a) \
    asm volatile("ldmatrix.sync.aligned.m8n8.x4.shared.b16 {%0,%1,%2,%3}, [%4];" \
                 : "=r"((r)[0]), "=r"((r)[1]), "=r"((r)[2]), "=r"((r)[3]) : "r"(a))

#define LDSM2(r, a) \
    asm volatile("ldmatrix.sync.aligned.m8n8.x2.shared.b16 {%0,%1}, [%2];" \
                 : "=r"((r)[0]), "=r"((r)[1]) : "r"(a))

#define MMA16816(c, a, b0, b1) \
    asm volatile("mma.sync.aligned.m16n8k16.row.col.f32.bf16.bf16.f32 " \
                 "{%0,%1,%2,%3}, {%4,%5,%6,%7}, {%8,%9}, {%0,%1,%2,%3};" \
                 : "+f"((c)[0]), "+f"((c)[1]), "+f"((c)[2]), "+f"((c)[3]) \
                 : "r"((a)[0]), "r"((a)[1]), "r"((a)[2]), "r"((a)[3]), \
                   "r"(b0), "r"(b1))

#define CP16(dst, src) \
    asm volatile("cp.async.cg.shared.global [%0], [%1], 16;" :: "r"(dst), "l"(src))
#define CP_COMMIT() asm volatile("cp.async.commit_group;")
#define CP_WAIT0()  asm volatile("cp.async.wait_group 0;")

#define BAR_SYNC(id)   asm volatile("bar.sync %0, 512;" :: "r"(id) : "memory")
#define BAR_ARRIVE(id) asm volatile("bar.arrive %0, 512;" :: "r"(id) : "memory")

// ---------------- prep kernels ----------------------------------------------
__global__ void pad_input_kernel(const float* __restrict__ x,
                                 float* __restrict__ pA, float* __restrict__ pB) {
    int i = blockIdx.x * 256 + threadIdx.x;
    if (i >= 4734976) return;
    int plane = i / PHW, rem = i - plane * PHW;
    int h = rem / PW - 2, w = rem % PW - 2;
    float v = 0.f;
    if (h >= 0 && h < 64 && w >= 0 && w < 64) v = x[plane * HWSZ + h * 64 + w];
    pA[i] = v;
    pB[i] = 0.f;
}

__global__ void prep_w_kernel(const float* __restrict__ w,
                              __nv_bfloat16* __restrict__ whi,
                              __nv_bfloat16* __restrict__ wlo) {
    int idx = blockIdx.x * 256 + threadIdx.x;
    if (idx >= 2359296) return;
    int r = idx / 589824;
    int rem = idx - r * 589824;
    int kb = rem >> 13;          // 0..71
    int rem2 = rem & 8191;
    int oc = rem2 >> 5;
    int j = rem2 & 31;
    int kk = kb >> 3;
    int c = ((kb & 7) << 5) + j;
    float v = w[(((r * 256 + oc) * 256 + c) * 9) + kk];
    __nv_bfloat16 h = __float2bfloat16_rn(v);
    whi[idx] = h;
    wlo[idx] = __float2bfloat16_rn(v - __bfloat162float(h));
}

__global__ void prep_offw_kernel(const float* __restrict__ offw,
                                 __nv_bfloat16* __restrict__ owhi,
                                 __nv_bfloat16* __restrict__ owlo) {
    int idx = blockIdx.x * 256 + threadIdx.x;
    if (idx >= 294912) return;
    int r = idx / 73728;
    int rem = idx - r * 73728;
    int kb = rem >> 11;
    int rem2 = rem & 2047;
    int ocp = rem2 >> 6;
    int j = rem2 & 63;
    int kk = kb >> 2;
    int c = ((kb & 3) << 6) + j;
    float v = (ocp < OC2) ? offw[((r * OC2 + ocp) * 256 + c) * 9 + kk] : 0.f;
    __nv_bfloat16 h = __float2bfloat16_rn(v);
    owhi[idx] = h;
    owlo[idx] = __float2bfloat16_rn(v - __bfloat162float(h));
}

// ---------------- helpers ----------------------------------------------------
static __device__ __forceinline__ void cvt_pair(float v0, float v1,
        uint32_t& hp, uint32_t& lp) {
    __nv_bfloat162 h2, l2;
    h2.x = __float2bfloat16_rn(v0);
    h2.y = __float2bfloat16_rn(v1);
    l2.x = __float2bfloat16_rn(v0 - __bfloat162float(h2.x));
    l2.y = __float2bfloat16_rn(v1 - __bfloat162float(h2.y));
    hp = *(uint32_t*)&h2;
    lp = *(uint32_t*)&l2;
}

// ---------------- fused layer kernel ----------------------------------------
// grid = 128 CTAs (4 b x 32 px-tiles of 128), 512 threads / 16 warps.
// Phase1: all threads, bf16 offset GEMM 32x128 (K-block 64).
// Phase2: warps 0-7 = MMA consumers (64oc x 64px tiles over 256x128 CTA tile),
//         warps 8-15 = producers (gather+interp+cvt+STS, A via cp.async),
//         double-buffered K-block 32, named-barrier full/empty protocol.
__global__ __launch_bounds__(512, 1) void fused_layer_kernel(
    const float* __restrict__ xpad,
    const __nv_bfloat16* __restrict__ owhi, const __nv_bfloat16* __restrict__ owlo,
    const float* __restrict__ offbias,
    const __nv_bfloat16* __restrict__ whi, const __nv_bfloat16* __restrict__ wlo,
    float* __restrict__ outp, int pad_out)
{
    extern __shared__ char smem[];
    uint32_t sb = smem_u32(smem);
    int tid = threadIdx.x;
    int lane = tid & 31;
    int wid = tid >> 5;
    int b = blockIdx.x >> 5;
    int px0 = (blockIdx.x & 31) << 7;

    // ================= PHASE 1: offset conv GEMM (D_off[32][128]) ==========
    {
        int px = tid & 127;
        int cg = tid >> 7;           // 0..3, 16 channels each
        int hpx = (px0 + px) >> 6;
        int wpx = (px0 + px) & 63;

        float acc1[2][4];
#pragma unroll
        for (int mi = 0; mi < 2; ++mi)
#pragma unroll
            for (int q = 0; q < 4; ++q) acc1[mi][q] = 0.f;

        for (int kb = 0; kb < 36; ++kb) {
            int kk = kb >> 2;
            if (kb) __syncthreads();

            if (tid < 256) {
                int row = tid >> 3, seg = tid & 7;
                uint32_t o = SW(row, seg << 4);
                *(uint4*)(smem + 0 + o) =
                    ((const uint4*)(owhi + ((size_t)kb << 11)))[tid];
                *(uint4*)(smem + 16384 + o) =
                    ((const uint4*)(owlo + ((size_t)kb << 11)))[tid];
            }
            {
                const float* xb = xpad + ((size_t)(b * 256) + ((kb & 3) << 6) + (cg << 4)) * PHW
                                + (hpx + kk / 3 + 1) * PW + (wpx + kk % 3 + 1);
                uint32_t hp[8], lp[8];
#pragma unroll
                for (int jj = 0; jj < 8; ++jj) {
                    float v0 = xb[(size_t)(jj << 1) * PHW];
                    float v1 = xb[(size_t)((jj << 1) + 1) * PHW];
                    cvt_pair(v0, v1, hp[jj], lp[jj]);
                }
                uint32_t o0 = SW(px, cg << 5);
                uint32_t o1 = SW(px, (cg << 5) + 16);
                *(uint4*)(smem + 32768 + o0) = make_uint4(hp[0], hp[1], hp[2], hp[3]);
                *(uint4*)(smem + 32768 + o1) = make_uint4(hp[4], hp[5], hp[6], hp[7]);
                *(uint4*)(smem + 49152 + o0) = make_uint4(lp[0], lp[1], lp[2], lp[3]);
                *(uint4*)(smem + 49152 + o1) = make_uint4(lp[4], lp[5], lp[6], lp[7]);
            }
            __syncthreads();

            int n_base = wid << 3;
#pragma unroll
            for (int ks = 0; ks < 4; ++ks) {
                uint32_t ah1[2][4], al1[2][4], bh1[2], bl1[2];
#pragma unroll
                for (int mi = 0; mi < 2; ++mi) {
                    int row = (mi << 4) + (lane & 15);
                    uint32_t o = SW(row, (ks << 5) + ((lane >> 4) << 4));
                    LDSM4(ah1[mi], sb + 0 + o);
                    LDSM4(al1[mi], sb + 16384 + o);
                }
                int brow = n_base + (lane & 7);
                uint32_t bo = SW(brow, (ks << 5) + (((lane >> 3) & 1) << 4));
                LDSM2(bh1, sb + 32768 + bo);
                LDSM2(bl1, sb + 49152 + bo);
#pragma unroll
                for (int mi = 0; mi < 2; ++mi) {
                    MMA16816(acc1[mi], ah1[mi], bh1[0], bh1[1]);
                    MMA16816(acc1[mi], al1[mi], bh1[0], bh1[1]);
                    MMA16816(acc1[mi], ah1[mi], bl1[0], bl1[1]);
                }
            }
        }
        __syncthreads();

        // offsets to smem @32768: offs[32][128] f32
        {
            float* offs = (float*)(smem + 32768);
#pragma unroll
            for (int mi = 0; mi < 2; ++mi) {
                int ocp = (mi << 4) + (lane >> 2);
                int pc = (wid << 3) + ((lane & 3) << 1);
                offs[ocp * 128 + pc] = acc1[mi][0];
                offs[ocp * 128 + pc + 1] = acc1[mi][1];
                offs[(ocp + 8) * 128 + pc] = acc1[mi][2];
                offs[(ocp + 8) * 128 + pc + 1] = acc1[mi][3];
            }
        }
        __syncthreads();

        // bilinear metadata
        {
            const float* offs = (const float*)(smem + 32768);
            int* sIdx = (int*)(smem + SM_IDX);
            float* sWy = (float*)(smem + SM_WY);
            float* sWx = (float*)(smem + SM_WX);
            for (int i = tid; i < 1152; i += 512) {
                int kk = i >> 7;
                int p = i & 127;
                int pix = px0 + p;
                int h = pix >> 6;
                int w = pix & 63;
                float dy = offs[((2 * kk) << 7) + p] + offbias[2 * kk];
                float dx = offs[((2 * kk + 1) << 7) + p] + offbias[2 * kk + 1];
                float py = fminf(fmaxf((float)(h + kk / 3 - 1) + dy, -1.5f), 64.5f);
                float pxx = fminf(fmaxf((float)(w + kk % 3 - 1) + dx, -1.5f), 64.5f);
                float y0f = floorf(py), x0f = floorf(pxx);
                sIdx[i] = ((int)y0f + 2) * PW + ((int)x0f + 2);
                sWy[i] = py - y0f;
                sWx[i] = pxx - x0f;
            }
        }
        __syncthreads();
    }

    // ================= PHASE 2: producer/consumer deform GEMM ==============
    if (wid >= 8) {
        // ---------------- PRODUCER (warps 8-15) ----------------
        int tid2 = tid - 256;
        int px = tid2 & 127;
        int cg = tid2 >> 7;          // 0/1: 16-channel half of the 32-ck block
        for (int kb = 0; kb < 72; ++kb) {
            uint32_t abuf = (kb & 1) ? SM_A1 : SM_A0;
            uint32_t bbuf = (kb & 1) ? SM_B1 : SM_B0;
            if (kb >= 2) BAR_SYNC(3 + (kb & 1));     // wait empty
            // A: 256oc x 32ck hi/lo via cp.async (8 chunks/thread each)
            {
                const char* ah = (const char*)whi + ((size_t)kb << 14);
                const char* al = (const char*)wlo + ((size_t)kb << 14);
#pragma unroll
                for (int t = 0; t < 4; ++t) {
                    int i = tid2 + (t << 8);
                    uint32_t o = SW64(i >> 2, (i & 3) << 4);
                    CP16(sb + abuf + o, ah + ((size_t)i << 4));
                    CP16(sb + abuf + 16384 + o, al + ((size_t)i << 4));
                }
                CP_COMMIT();
            }
            // B: gather + interp + cvt + STS, 16 channels
            {
                int kk = kb >> 3;
                int mi_ = kk * 128 + px;
                int idx0 = ((const int*)(smem + SM_IDX))[mi_];
                float wy = ((const float*)(smem + SM_WY))[mi_];
                float wx = ((const float*)(smem + SM_WX))[mi_];
                float w01 = (1.f - wy) * wx;
                float w00 = (1.f - wy) - w01;
                float w11 = wy * wx;
                float w10 = wy - w11;
                const float* xb = xpad + ((size_t)(b * 256) + ((kb & 7) << 5) + (cg << 4)) * PHW + idx0;
                uint32_t hp[8], lp[8];
#pragma unroll
                for (int jj = 0; jj < 8; ++jj) {
                    const float* p0 = xb + (size_t)(jj << 1) * PHW;
                    const float* p1 = p0 + PHW;
                    float v0 = fmaf(w11, p0[PW + 1], fmaf(w10, p0[PW], fmaf(w01, p0[1], w00 * p0[0])));
                    float v1 = fmaf(w11, p1[PW + 1], fmaf(w10, p1[PW], fmaf(w01, p1[1], w00 * p1[0])));
                    cvt_pair(v0, v1, hp[jj], lp[jj]);
                }
                uint32_t o0 = SW64(px, cg << 5);
                uint32_t o1 = SW64(px, (cg << 5) + 16);
                *(uint4*)(smem + bbuf + o0) = make_uint4(hp[0], hp[1], hp[2], hp[3]);
                *(uint4*)(smem + bbuf + o1) = make_uint4(hp[4], hp[5], hp[6], hp[7]);
                *(uint4*)(smem + bbuf + 8192 + o0) = make_uint4(lp[0], lp[1], lp[2], lp[3]);
                *(uint4*)(smem + bbuf + 8192 + o1) = make_uint4(lp[4], lp[5], lp[6], lp[7]);
            }
            CP_WAIT0();
            BAR_ARRIVE(1 + (kb & 1));               // signal full
        }
        __syncthreads();
    } else {
        // ---------------- CONSUMER (warps 0-7): 64oc x 64px tiles ----------
        float acc[4][8][4];
#pragma unroll
        for (int mi = 0; mi < 4; ++mi)
#pragma unroll
            for (int nj = 0; nj < 8; ++nj)
#pragma unroll
                for (int q = 0; q < 4; ++q) acc[mi][nj][q] = 0.f;

        int m_base = (wid & 3) << 6;     // 0..192
        int n_base = (wid >> 2) << 6;    // 0 or 64

        for (int kb = 0; kb < 72; ++kb) {
            uint32_t abuf = (kb & 1) ? SM_A1 : SM_A0;
            uint32_t bbuf = (kb & 1) ? SM_B1 : SM_B0;
            BAR_SYNC(1 + (kb & 1));                 // wait full
#pragma unroll
            for (int ks = 0; ks < 2; ++ks) {
                uint32_t a_[4][4], bf[4][4];
                int arow0 = m_base + (lane & 15);
                uint32_t acolb = (uint32_t)((ks << 5) + ((lane >> 4) << 4));
                int brow0 = n_base + ((lane >> 4) << 3) + (lane & 7);
                uint32_t bcolb = (uint32_t)((ks << 5) + (((lane >> 3) & 1) << 4));
#pragma unroll
                for (int np = 0; np < 4; ++np)
                    LDSM4(bf[np], sb + bbuf + SW64(brow0 + (np << 4), bcolb));   // B hi
#pragma unroll
                for (int mi = 0; mi < 4; ++mi)
                    LDSM4(a_[mi], sb + abuf + 16384 + SW64(arow0 + (mi << 4), acolb)); // A lo
#pragma unroll
                for (int mi = 0; mi < 4; ++mi)
#pragma unroll
                    for (int nj = 0; nj < 8; ++nj)
                        MMA16816(acc[mi][nj], a_[mi], bf[nj >> 1][(nj & 1) * 2],
                                 bf[nj >> 1][(nj & 1) * 2 + 1]);
#pragma unroll
                for (int mi = 0; mi < 4; ++mi)
                    LDSM4(a_[mi], sb + abuf + SW64(arow0 + (mi << 4), acolb));   // A hi
#pragma unroll
                for (int mi = 0; mi < 4; ++mi)
#pragma unroll
                    for (int nj = 0; nj < 8; ++nj)
                        MMA16816(acc[mi][nj], a_[mi], bf[nj >> 1][(nj & 1) * 2],
                                 bf[nj >> 1][(nj & 1) * 2 + 1]);
#pragma unroll
                for (int np = 0; np < 4; ++np)
                    LDSM4(bf[np], sb + bbuf + 8192 + SW64(brow0 + (np << 4), bcolb)); // B lo
#pragma unroll
                for (int mi = 0; mi < 4; ++mi)
#pragma unroll
                    for (int nj = 0; nj < 8; ++nj)
                        MMA16816(acc[mi][nj], a_[mi], bf[nj >> 1][(nj & 1) * 2],
                                 bf[nj >> 1][(nj & 1) * 2 + 1]);
            }
            BAR_ARRIVE(3 + (kb & 1));               // signal empty
        }
        __syncthreads();

        // epilogue: relu + direct v2 stores
        int plane = pad_out ? PHW : HWSZ;
        int ostride = pad_out ? PW : 64;
        int obase = pad_out ? PBASE : 0;
#pragma unroll
        for (int mi = 0; mi < 4; ++mi) {
#pragma unroll
            for (int nj = 0; nj < 8; ++nj) {
                int row = m_base + (mi << 4) + (lane >> 2);
                int colp = n_base + (nj << 3) + ((lane & 3) << 1);
                int pix = px0 + colp;
                int h = pix >> 6;
                int wv = pix & 63;
                float* d0 = outp + (size_t)(b * 256 + row) * plane + h * ostride + wv + obase;
                float* d1 = outp + (size_t)(b * 256 + row + 8) * plane + h * ostride + wv + obase;
                float2 v0, v1;
                v0.x = fmaxf(acc[mi][nj][0], 0.f);
                v0.y = fmaxf(acc[mi][nj][1], 0.f);
                v1.x = fmaxf(acc[mi][nj][2], 0.f);
                v1.y = fmaxf(acc[mi][nj][3], 0.f);
                *(float2*)d0 = v0;
                *(float2*)d1 = v1;
            }
        }
    }
}

// ---------------- launch ----------------------------------------------------
extern "C" void kernel_launch(void* const* d_in, const int* in_sizes, int n_in,
                              void* d_out, int out_size) {
    (void)in_sizes; (void)n_in; (void)out_size;
    const float* x    = (const float*)d_in[0];
    const float* offw = (const float*)d_in[1];
    const float* offb = (const float*)d_in[2];
    const float* w    = (const float*)d_in[3];
    float* out = (float*)d_out;

    float *padA, *padB;
    __nv_bfloat16 *gwhi, *gwlo, *gowhi, *gowlo;
    cudaGetSymbolAddress((void**)&padA, g_padA);
    cudaGetSymbolAddress((void**)&padB, g_padB);
    cudaGetSymbolAddress((void**)&gwhi, g_whi);
    cudaGetSymbolAddress((void**)&gwlo, g_wlo);
    cudaGetSymbolAddress((void**)&gowhi, g_owhi);
    cudaGetSymbolAddress((void**)&gowlo, g_owlo);

    cudaFuncSetAttribute(fused_layer_kernel,
                         cudaFuncAttributeMaxDynamicSharedMemorySize, SM_TOTAL);

    pad_input_kernel<<<(4734976 + 255) / 256, 256>>>(x, padA, padB);
    prep_w_kernel<<<(2359296 + 255) / 256, 256>>>(w, gwhi, gwlo);
    prep_offw_kernel<<<(294912 + 255) / 256, 256>>>(offw, gowhi, gowlo);

    const float* cur = padA;
    for (int r = 0; r < RB; ++r) {
        int last = (r == 3);
        float* nxt = last ? out : ((r & 1) == 0 ? padB : padA);
        fused_layer_kernel<<<128, 512, SM_TOTAL>>>(
            cur, gowhi + (size_t)r * 73728, gowlo + (size_t)r * 73728,
            offb + r * OC2, gwhi + (size_t)r * 589824, gwlo + (size_t)r * 589824,
            nxt, last ? 0 : 1);
        cur = nxt;
    }
}

// round 16
// speedup vs baseline: 2.1055x; 2.1055x over previous
#include <cuda_runtime.h>
#include <cuda_bf16.h>
#include <math.h>
#include <stdint.h>

#define RB 4
#define CC 256
#define HWSZ 4096
#define OC2 18

// ---------------- smem layout (bytes, dynamic) ---------------
#define SM_A     0                      // A_hi [256 oc][64 ck] bf16 = 32768 (phase1: 32x64 = 4KB)
#define SM_ALO   32768                  // A_lo
#define SM_BHI   65536                  // B_hi [128 px][64 ck] bf16 = 16384 ; phase1 offs result [32][128] f32
#define SM_BLO   81920
#define SM_MIDX  98304                  // int   [9][128][4] = 18432
#define SM_MW    116736                 // float [9][128][4] = 18432
#define SM_TOTAL 135168

// ---------------- scratch (device globals; no allocations allowed) ----------
__device__ float g_bufA[4194304];
__device__ float g_bufB[4194304];
// main weights reordered: [r][kb=cb*9+kk (36)][oc (256)][j (64)], c = cb*64+j
__device__ __align__(16) __nv_bfloat16 g_whi[2359296];
__device__ __align__(16) __nv_bfloat16 g_wlo[2359296];
// offset-conv weights reordered: [r][kb=cb*9+kk (36)][ocp (32, pad from 18)][j (64)]
__device__ __align__(16) __nv_bfloat16 g_owhi[294912];
__device__ __align__(16) __nv_bfloat16 g_owlo[294912];

// ---------------- PTX helpers ----------------------------------------------
static __device__ __forceinline__ uint32_t smem_u32(const void* p) {
    uint32_t a;
    asm("{ .reg .u64 t; cvta.to.shared.u64 t, %1; cvt.u32.u64 %0, t; }" : "=r"(a) : "l"(p));
    return a;
}

#define LDSM4(r, a) \
    asm volatile("ldmatrix.sync.aligned.m8n8.x4.shared.b16 {%0,%1,%2,%3}, [%4];" \
                 : "=r"((r)[0]), "=r"((r)[1]), "=r"((r)[2]), "=r"((r)[3]) : "r"(a))

#define LDSM2(r, a) \
    asm volatile("ldmatrix.sync.aligned.m8n8.x2.shared.b16 {%0,%1}, [%2];" \
                 : "=r"((r)[0]), "=r"((r)[1]) : "r"(a))

#define MMA16816(c, a, b0, b1) \
    asm volatile("mma.sync.aligned.m16n8k16.row.col.f32.bf16.bf16.f32 " \
                 "{%0,%1,%2,%3}, {%4,%5,%6,%7}, {%8,%9}, {%0,%1,%2,%3};" \
                 : "+f"((c)[0]), "+f"((c)[1]), "+f"((c)[2]), "+f"((c)[3]) \
                 : "r"((a)[0]), "r"((a)[1]), "r"((a)[2]), "r"((a)[3]), \
                   "r"(b0), "r"(b1))

// ---------------- weight prep: fp32 -> bf16 hi/lo, reordered (tap-inner) ----
__global__ void prep_w_kernel(const float* __restrict__ w,
                              __nv_bfloat16* __restrict__ whi,
                              __nv_bfloat16* __restrict__ wlo) {
    int idx = blockIdx.x * 256 + threadIdx.x;
    if (idx >= 2359296) return;
    int r = idx / 589824;
    int rem = idx - r * 589824;
    int kb = rem >> 14;          // 0..35 = cb*9 + kk
    int rem2 = rem & 16383;
    int oc = rem2 >> 6;
    int j = rem2 & 63;
    int kk = kb % 9;
    int cb = kb / 9;
    int c = (cb << 6) + j;
    float v = w[(((r * 256 + oc) * 256 + c) * 9) + kk];
    __nv_bfloat16 h = __float2bfloat16_rn(v);
    whi[idx] = h;
    wlo[idx] = __float2bfloat16_rn(v - __bfloat162float(h));
}

__global__ void prep_offw_kernel(const float* __restrict__ offw,
                                 __nv_bfloat16* __restrict__ owhi,
                                 __nv_bfloat16* __restrict__ owlo) {
    int idx = blockIdx.x * 256 + threadIdx.x;
    if (idx >= 294912) return;
    int r = idx / 73728;
    int rem = idx - r * 73728;
    int kb = rem >> 11;          // 0..35 = cb*9 + kk
    int rem2 = rem & 2047;
    int ocp = rem2 >> 6;
    int j = rem2 & 63;
    int kk = kb % 9;
    int cb = kb / 9;
    int c = (cb << 6) + j;
    float v = (ocp < OC2) ? offw[((r * OC2 + ocp) * 256 + c) * 9 + kk] : 0.f;
    __nv_bfloat16 h = __float2bfloat16_rn(v);
    owhi[idx] = h;
    owlo[idx] = __float2bfloat16_rn(v - __bfloat162float(h));
}

// ---------------- fused layer: offset conv GEMM + deform GEMM ---------------
// grid = 128 CTAs (4 batches x 32 px-tiles of 128), 512 threads / 16 warps.
__global__ __launch_bounds__(512, 1) void fused_layer_kernel(
    const float* __restrict__ x,
    const __nv_bfloat16* __restrict__ owhi, const __nv_bfloat16* __restrict__ owlo,
    const float* __restrict__ offbias,
    const __nv_bfloat16* __restrict__ whi, const __nv_bfloat16* __restrict__ wlo,
    float* __restrict__ out)
{
    extern __shared__ char smem[];
    uint32_t sb = smem_u32(smem);
    int tid = threadIdx.x;
    int lane = tid & 31;
    int wid = tid >> 5;
    int b = blockIdx.x >> 5;
    int px0 = (blockIdx.x & 31) << 7;

    int px = tid & 127;
    int cg = tid >> 7;           // 0..3: 16-channel group
    int hpx = (px0 + px) >> 6;   // this pixel's row
    int wpx = (px0 + px) & 63;

    // ================= PHASE 1: offset conv GEMM (D_off[32][128]) ==========
    float acc1[2][4];
#pragma unroll
    for (int mi = 0; mi < 2; ++mi)
#pragma unroll
        for (int q = 0; q < 4; ++q) acc1[mi][q] = 0.f;

    for (int cb = 0; cb < 4; ++cb) {
        for (int kk = 0; kk < 9; ++kk) {
            int kb = cb * 9 + kk;
            if (kb) __syncthreads();

            // stage A_off hi/lo: 32 rows x 64 ck (4KB each)
            if (tid < 256) {
                const uint4* ah = (const uint4*)(owhi + ((size_t)kb << 11));
                const uint4* al = (const uint4*)(owlo + ((size_t)kb << 11));
                int row = tid >> 3, seg = tid & 7;
                uint32_t o = ((uint32_t)row << 7) + (((uint32_t)seg << 4) ^ ((row & 7) << 4));
                *(uint4*)(smem + SM_A + o) = ah[tid];
                *(uint4*)(smem + SM_ALO + o) = al[tid];
            }

            // stage B im2col: [128 px][64 ck], tap kk, c-block cb
            {
                int hh = hpx + kk / 3 - 1;
                int ww = wpx + kk % 3 - 1;
                bool valid = (hh >= 0) && (hh < 64) && (ww >= 0) && (ww < 64);
                int src = valid ? hh * 64 + ww : 0;
                const float* xb = x + ((size_t)(b * 256) + (cb << 6) + (cg << 4)) * HWSZ + src;
                uint32_t hp[8], lp[8];
#pragma unroll
                for (int jj = 0; jj < 8; ++jj) {
                    float v0 = valid ? xb[(size_t)(jj << 1) * HWSZ] : 0.f;
                    float v1 = valid ? xb[(size_t)((jj << 1) + 1) * HWSZ] : 0.f;
                    __nv_bfloat162 h2, l2;
                    h2.x = __float2bfloat16_rn(v0);
                    h2.y = __float2bfloat16_rn(v1);
                    l2.x = __float2bfloat16_rn(v0 - __bfloat162float(h2.x));
                    l2.y = __float2bfloat16_rn(v1 - __bfloat162float(h2.y));
                    hp[jj] = *(uint32_t*)&h2;
                    lp[jj] = *(uint32_t*)&l2;
                }
                uint32_t rb = (uint32_t)px << 7;
                uint32_t xm = ((uint32_t)px & 7) << 4;
                uint32_t c0b = (uint32_t)cg << 5;
                uint32_t o0 = rb + (c0b ^ xm);
                uint32_t o1 = rb + ((c0b + 16) ^ xm);
                *(uint4*)(smem + SM_BHI + o0) = make_uint4(hp[0], hp[1], hp[2], hp[3]);
                *(uint4*)(smem + SM_BHI + o1) = make_uint4(hp[4], hp[5], hp[6], hp[7]);
                *(uint4*)(smem + SM_BLO + o0) = make_uint4(lp[0], lp[1], lp[2], lp[3]);
                *(uint4*)(smem + SM_BLO + o1) = make_uint4(lp[4], lp[5], lp[6], lp[7]);
            }
            __syncthreads();

            // mma: warp wid covers n8 col = wid*8, two m16 halves
            int n_base = wid << 3;
#pragma unroll
            for (int ks = 0; ks < 4; ++ks) {
                uint32_t ah1[2][4], al1[2][4], bh1[2], bl1[2];
#pragma unroll
                for (int mi = 0; mi < 2; ++mi) {
                    int row = (mi << 4) + (lane & 15);
                    uint32_t o = ((uint32_t)row << 7) +
                                 ((uint32_t)((ks << 5) + ((lane >> 4) << 4)) ^ ((row & 7) << 4));
                    LDSM4(ah1[mi], sb + SM_A + o);
                    LDSM4(al1[mi], sb + SM_ALO + o);
                }
                int brow = n_base + (lane & 7);
                uint32_t bo = ((uint32_t)brow << 7) +
                              ((uint32_t)((ks << 5) + (((lane >> 3) & 1) << 4)) ^ ((brow & 7) << 4));
                LDSM2(bh1, sb + SM_BHI + bo);
                LDSM2(bl1, sb + SM_BLO + bo);
#pragma unroll
                for (int mi = 0; mi < 2; ++mi) {
                    MMA16816(acc1[mi], ah1[mi], bh1[0], bh1[1]);
                    MMA16816(acc1[mi], al1[mi], bh1[0], bh1[1]);
                    MMA16816(acc1[mi], ah1[mi], bl1[0], bl1[1]);
                }
            }
        }
    }
    __syncthreads();

    // write offsets to smem (reuse SM_BHI region): offs[32][128] f32
    {
        float* offs = (float*)(smem + SM_BHI);
#pragma unroll
        for (int mi = 0; mi < 2; ++mi) {
            int ocp = (mi << 4) + (lane >> 2);
            int pc = (wid << 3) + ((lane & 3) << 1);
            offs[ocp * 128 + pc] = acc1[mi][0];
            offs[ocp * 128 + pc + 1] = acc1[mi][1];
            offs[(ocp + 8) * 128 + pc] = acc1[mi][2];
            offs[(ocp + 8) * 128 + pc + 1] = acc1[mi][3];
        }
    }
    __syncthreads();

    // ---- bilinear metadata from smem offsets ----
    int* midx = (int*)(smem + SM_MIDX);
    float* mwgt = (float*)(smem + SM_MW);
    {
        const float* offs = (const float*)(smem + SM_BHI);
        for (int i = tid; i < 1152; i += 512) {
            int kk = i >> 7;
            int p = i & 127;
            int pix = px0 + p;
            int h = pix >> 6;
            int w = pix & 63;
            float dy = offs[((2 * kk) << 7) + p] + offbias[2 * kk];
            float dx = offs[((2 * kk + 1) << 7) + p] + offbias[2 * kk + 1];
            float py = (float)(h + kk / 3 - 1) + dy;
            float px_ = (float)(w + kk % 3 - 1) + dx;
            float y0f = floorf(py), x0f = floorf(px_);
            int y0 = (int)y0f, x0 = (int)x0f;
            float wy = py - y0f, wx = px_ - x0f;
            float cw[4];
            int cy[4], cx[4];
            cw[0] = (1.f - wy) * (1.f - wx); cy[0] = y0;     cx[0] = x0;
            cw[1] = (1.f - wy) * wx;         cy[1] = y0;     cx[1] = x0 + 1;
            cw[2] = wy * (1.f - wx);         cy[2] = y0 + 1; cx[2] = x0;
            cw[3] = wy * wx;                 cy[3] = y0 + 1; cx[3] = x0 + 1;
#pragma unroll
            for (int q = 0; q < 4; ++q) {
                bool valid = (cy[q] >= 0) && (cy[q] < 64) && (cx[q] >= 0) && (cx[q] < 64);
                int yy = cy[q] < 0 ? 0 : (cy[q] > 63 ? 63 : cy[q]);
                int xx = cx[q] < 0 ? 0 : (cx[q] > 63 ? 63 : cx[q]);
                midx[i * 4 + q] = yy * 64 + xx;
                mwgt[i * 4 + q] = valid ? cw[q] : 0.f;
            }
        }
    }
    __syncthreads();

    // ================= PHASE 2: deform GEMM (D[256][128]) ==================
    float acc[4][4][4];
#pragma unroll
    for (int mi = 0; mi < 4; ++mi)
#pragma unroll
        for (int nj = 0; nj < 4; ++nj)
#pragma unroll
            for (int q = 0; q < 4; ++q) acc[mi][nj][q] = 0.f;

    int m_base = (wid & 3) << 6;
    int n_base = (wid >> 2) << 5;

    for (int cb = 0; cb < 4; ++cb) {
        for (int kk = 0; kk < 9; ++kk) {
            int kb = cb * 9 + kk;
            if (kb) __syncthreads();

            // stage A (weights) hi/lo: [256 oc][64 ck] swizzled
            {
                const uint4* ah = (const uint4*)(whi + ((size_t)kb << 14));
                const uint4* al = (const uint4*)(wlo + ((size_t)kb << 14));
#pragma unroll
                for (int t = 0; t < 4; ++t) {
                    int i = tid + (t << 9);
                    int row = i >> 3, seg = i & 7;
                    uint32_t o = ((uint32_t)row << 7) + (((uint32_t)seg << 4) ^ ((row & 7) << 4));
                    *(uint4*)(smem + SM_A + o) = ah[i];
                    *(uint4*)(smem + SM_ALO + o) = al[i];
                }
            }

            // sample B tile: [128 px][64 ck] tap kk
            {
                const int* mi_ = &midx[(kk * 128 + px) * 4];
                const float* mw_ = &mwgt[(kk * 128 + px) * 4];
                int i0 = mi_[0], i1 = mi_[1], i2 = mi_[2], i3 = mi_[3];
                float w0 = mw_[0], w1 = mw_[1], w2 = mw_[2], w3 = mw_[3];
                const float* xb = x + ((size_t)(b * 256) + (cb << 6) + (cg << 4)) * HWSZ;
                uint32_t hp[8], lp[8];
#pragma unroll
                for (int jj = 0; jj < 8; ++jj) {
                    const float* p0 = xb + (size_t)(jj << 1) * HWSZ;
                    const float* p1 = p0 + HWSZ;
                    float v0 = fmaf(w3, p0[i3], fmaf(w2, p0[i2], fmaf(w1, p0[i1], w0 * p0[i0])));
                    float v1 = fmaf(w3, p1[i3], fmaf(w2, p1[i2], fmaf(w1, p1[i1], w0 * p1[i0])));
                    __nv_bfloat162 h2, l2;
                    h2.x = __float2bfloat16_rn(v0);
                    h2.y = __float2bfloat16_rn(v1);
                    l2.x = __float2bfloat16_rn(v0 - __bfloat162float(h2.x));
                    l2.y = __float2bfloat16_rn(v1 - __bfloat162float(h2.y));
                    hp[jj] = *(uint32_t*)&h2;
                    lp[jj] = *(uint32_t*)&l2;
                }
                uint32_t rb = (uint32_t)px << 7;
                uint32_t xm = ((uint32_t)px & 7) << 4;
                uint32_t c0b = (uint32_t)cg << 5;
                uint32_t o0 = rb + (c0b ^ xm);
                uint32_t o1 = rb + ((c0b + 16) ^ xm);
                *(uint4*)(smem + SM_BHI + o0) = make_uint4(hp[0], hp[1], hp[2], hp[3]);
                *(uint4*)(smem + SM_BHI + o1) = make_uint4(hp[4], hp[5], hp[6], hp[7]);
                *(uint4*)(smem + SM_BLO + o0) = make_uint4(lp[0], lp[1], lp[2], lp[3]);
                *(uint4*)(smem + SM_BLO + o1) = make_uint4(lp[4], lp[5], lp[6], lp[7]);
            }
            __syncthreads();

            // ldmatrix + mma: 4 k16-steps
#pragma unroll
            for (int ks = 0; ks < 4; ++ks) {
                uint32_t ah_[4][4], al_[4][4], bf[2][4];
                int arow0 = m_base + (lane & 15);
                uint32_t acolb = (uint32_t)((ks << 5) + ((lane >> 4) << 4));
#pragma unroll
                for (int mi = 0; mi < 4; ++mi) {
                    int row = arow0 + (mi << 4);
                    uint32_t o = ((uint32_t)row << 7) + (acolb ^ ((row & 7) << 4));
                    LDSM4(ah_[mi], sb + SM_A + o);
                    LDSM4(al_[mi], sb + SM_ALO + o);
                }
                int brow0 = n_base + ((lane >> 4) << 3) + (lane & 7);
                uint32_t bcolb = (uint32_t)((ks << 5) + (((lane >> 3) & 1) << 4));
#pragma unroll
                for (int np = 0; np < 2; ++np) {
                    int row = brow0 + (np << 4);
                    uint32_t o = ((uint32_t)row << 7) + (bcolb ^ ((row & 7) << 4));
                    LDSM4(bf[np], sb + SM_BHI + o);
                }
#pragma unroll
                for (int mi = 0; mi < 4; ++mi)
#pragma unroll
                    for (int nj = 0; nj < 4; ++nj) {
                        MMA16816(acc[mi][nj], ah_[mi], bf[nj >> 1][(nj & 1) * 2], bf[nj >> 1][(nj & 1) * 2 + 1]);
                        MMA16816(acc[mi][nj], al_[mi], bf[nj >> 1][(nj & 1) * 2], bf[nj >> 1][(nj & 1) * 2 + 1]);
                    }
#pragma unroll
                for (int np = 0; np < 2; ++np) {
                    int row = brow0 + (np << 4);
                    uint32_t o = ((uint32_t)row << 7) + (bcolb ^ ((row & 7) << 4));
                    LDSM4(bf[np], sb + SM_BLO + o);
                }
#pragma unroll
                for (int mi = 0; mi < 4; ++mi)
#pragma unroll
                    for (int nj = 0; nj < 4; ++nj)
                        MMA16816(acc[mi][nj], ah_[mi], bf[nj >> 1][(nj & 1) * 2], bf[nj >> 1][(nj & 1) * 2 + 1]);
            }
        }
    }

    // ---- epilogue: relu + direct v2 stores ----
    float* outb = out + (size_t)b * CC * HWSZ + px0;
#pragma unroll
    for (int mi = 0; mi < 4; ++mi) {
#pragma unroll
        for (int nj = 0; nj < 4; ++nj) {
            int row = m_base + (mi << 4) + (lane >> 2);
            int colp = n_base + (nj << 3) + ((lane & 3) << 1);
            float2 v0, v1;
            v0.x = fmaxf(acc[mi][nj][0], 0.f);
            v0.y = fmaxf(acc[mi][nj][1], 0.f);
            v1.x = fmaxf(acc[mi][nj][2], 0.f);
            v1.y = fmaxf(acc[mi][nj][3], 0.f);
            *(float2*)(outb + (size_t)row * HWSZ + colp) = v0;
            *(float2*)(outb + (size_t)(row + 8) * HWSZ + colp) = v1;
        }
    }
}

// ---------------- launch ----------------------------------------------------
extern "C" void kernel_launch(void* const* d_in, const int* in_sizes, int n_in,
                              void* d_out, int out_size) {
    (void)in_sizes; (void)n_in; (void)out_size;
    const float* x    = (const float*)d_in[0];
    const float* offw = (const float*)d_in[1];
    const float* offb = (const float*)d_in[2];
    const float* w    = (const float*)d_in[3];
    float* out = (float*)d_out;

    float *bufA, *bufB;
    __nv_bfloat16 *gwhi, *gwlo, *gowhi, *gowlo;
    cudaGetSymbolAddress((void**)&bufA, g_bufA);
    cudaGetSymbolAddress((void**)&bufB, g_bufB);
    cudaGetSymbolAddress((void**)&gwhi, g_whi);
    cudaGetSymbolAddress((void**)&gwlo, g_wlo);
    cudaGetSymbolAddress((void**)&gowhi, g_owhi);
    cudaGetSymbolAddress((void**)&gowlo, g_owlo);

    cudaFuncSetAttribute(fused_layer_kernel,
                         cudaFuncAttributeMaxDynamicSharedMemorySize, SM_TOTAL);

    prep_w_kernel<<<(2359296 + 255) / 256, 256>>>(w, gwhi, gwlo);
    prep_offw_kernel<<<(294912 + 255) / 256, 256>>>(offw, gowhi, gowlo);

    const float* cur = x;
    for (int r = 0; r < RB; ++r) {
        float* nxt = (r == 3) ? out : ((r & 1) == 0 ? bufA : bufB);
        fused_layer_kernel<<<128, 512, SM_TOTAL>>>(
            cur, gowhi + (size_t)r * 73728, gowlo + (size_t)r * 73728,
            offb + r * OC2, gwhi + (size_t)r * 589824, gwlo + (size_t)r * 589824, nxt);
        cur = nxt;
    }
}